// round 15
// baseline (speedup 1.0000x reference)
#include <cuda_runtime.h>
#include <cstdint>

#define NN 50000
#define NE 640000

// Scratch (allocation-free per harness rules)
__device__ float g_deg[NN];
__device__ float g_agg[NN * 128];
__device__ float g_h[NN * 128];

// ============================ f32x2 helpers ============================

__device__ __forceinline__ unsigned long long pack2(float a, float b) {
    unsigned long long r;
    asm("mov.b64 %0, {%1, %2};" : "=l"(r) : "f"(a), "f"(b));
    return r;
}
__device__ __forceinline__ void unpack2(unsigned long long v, float& lo, float& hi) {
    asm("mov.b64 {%0, %1}, %2;" : "=f"(lo), "=f"(hi) : "l"(v));
}
__device__ __forceinline__ void fma2(unsigned long long& d, unsigned long long a,
                                     unsigned long long b) {
    asm("fma.rn.f32x2 %0, %1, %2, %0;" : "+l"(d) : "l"(a), "l"(b));
}

// ============================ zero / scatter ============================

__global__ void zero_kernel(float4* __restrict__ p, int n4) {
    int i = blockIdx.x * blockDim.x + threadIdx.x;
    int st = gridDim.x * blockDim.x;
    float4 z = make_float4(0.f, 0.f, 0.f, 0.f);
    for (; i < n4; i += st) p[i] = z;
}

template <int K, bool DO_DEG>
__global__ void scatter_kernel(const int* __restrict__ src, const int* __restrict__ dst,
                               const float* __restrict__ x, float* __restrict__ agg,
                               float* __restrict__ deg) {
    const int C = K / 4;
    const int total = NE * C;
    int i = blockIdx.x * blockDim.x + threadIdx.x;
    int st = gridDim.x * blockDim.x;
    for (; i < total; i += st) {
        int e = i / C;
        int c = i - e * C;
        int s = __ldg(src + e);
        int d = __ldg(dst + e);
        float4 v = __ldg((const float4*)x + (size_t)s * C + c);
        float* a = agg + (size_t)d * K + c * 4;
        asm volatile("red.global.add.v4.f32 [%0], {%1,%2,%3,%4};"
                     :: "l"(a), "f"(v.x), "f"(v.y), "f"(v.z), "f"(v.w)
                     : "memory");
        if (DO_DEG && c == 0) atomicAdd(deg + d, 1.0f);
    }
}

// ============================ f32x2 layer kernel ============================
// out[n, j] = (RELU?) b[j] + sum_k Wl[j,k]*mean[n,k] + Wr[j,k]*x[n,k]
// Combined K' = 2*KIN (mean ‖ x).  Block = 256 threads, tile = 64 nodes.
// smem: Ws[k'][j] transposed W (stride 132 to kill staging conflicts),
//       xsT[k'][node] transposed activations (stride 68) -> node-pair LDS.64
//       loads feed fma.rn.f32x2 directly, no packing movs on the x side.
// Warp w: 8 nodes (4 pairs). Lane: 4 outputs (jg..jg+3).
// Accumulators: acc[pair][j] packed over the node pair -> 16 fma2 per k-step.

template <int KIN, bool RELU>
__global__ void __launch_bounds__(256)
layer2x_kernel(const float* __restrict__ Wl, const float* __restrict__ bl,
               const float* __restrict__ Wr, const float* __restrict__ xin,
               const float* __restrict__ agg, const float* __restrict__ deg,
               float* __restrict__ out) {
    constexpr int K2 = 2 * KIN;
    constexpr int C4 = K2 / 4;     // float4 quads per combined row
    constexpr int WST = 132;       // Ws row stride (floats); 4*132 % 32 = 16 -> 2-way only
    constexpr int XST = 68;        // xsT row stride; even (LDS.64 align), 4*68 % 32 = 16
    extern __shared__ float sm[];
    float* Ws  = sm;               // K2 * WST
    float* xsT = Ws + K2 * WST;    // K2 * XST

    const int tid = threadIdx.x;
    const int wid = tid >> 5;
    const int lane = tid & 31;
    const int jg = lane * 4;       // 4 consecutive outputs per lane
    const int wb = wid * 8;        // warp's node base within the 64-node tile

    // ---- stage combined W transposed (once per block) ----
    // thread handles (j, quad): coalesced float4 reads along k, 2-way-conflict STS.
    for (int i = tid; i < 128 * C4; i += 256) {
        int j = i / C4;
        int q = i - j * C4;
        int k = q * 4;
        float4 v = (k < KIN) ? __ldg((const float4*)(Wl + j * KIN + k))
                             : __ldg((const float4*)(Wr + j * KIN + (k - KIN)));
        Ws[(k + 0) * WST + j] = v.x;
        Ws[(k + 1) * WST + j] = v.y;
        Ws[(k + 2) * WST + j] = v.z;
        Ws[(k + 3) * WST + j] = v.w;
    }

    // bias, packed once
    unsigned long long b2[4];
#pragma unroll
    for (int jj = 0; jj < 4; jj++) {
        float b = __ldg(bl + jg + jj);
        b2[jj] = pack2(b, b);
    }

    const int ntiles = (NN + 63) / 64;
    for (int t = blockIdx.x; t < ntiles; t += gridDim.x) {
        const int base = t * 64;
        __syncthreads();   // xsT safe to overwrite (also orders W staging on t==first)

        // ---- stage xsT for 64 nodes: coalesced float4 per node row ----
        for (int i = tid; i < 64 * C4; i += 256) {
            int nl = i / C4;
            int q  = i - nl * C4;
            int node = base + nl;
            if (node < NN) {
                float4 v;
                int k = q * 4;
                if (k < KIN) {
                    v = __ldg((const float4*)agg + node * (KIN / 4) + q);
                    float inv = 1.0f / fmaxf(__ldg(deg + node), 1.0f);
                    v.x *= inv; v.y *= inv; v.z *= inv; v.w *= inv;
                } else {
                    v = __ldg((const float4*)xin + node * (KIN / 4) + (q - KIN / 4));
                }
                xsT[(k + 0) * XST + nl] = v.x;
                xsT[(k + 1) * XST + nl] = v.y;
                xsT[(k + 2) * XST + nl] = v.z;
                xsT[(k + 3) * XST + nl] = v.w;
            }
        }
        __syncthreads();

        unsigned long long acc[4][4];
#pragma unroll
        for (int np = 0; np < 4; np++)
#pragma unroll
            for (int jj = 0; jj < 4; jj++) acc[np][jj] = b2[jj];

#pragma unroll 4
        for (int k = 0; k < K2; k++) {
            const float* xr = xsT + k * XST + wb;
            unsigned long long x2[4];
#pragma unroll
            for (int np = 0; np < 4; np++)
                x2[np] = *(const unsigned long long*)(xr + 2 * np);  // LDS.64 broadcast
            float4 w = *(const float4*)(Ws + k * WST + jg);          // LDS.128
            unsigned long long w2[4] = { pack2(w.x, w.x), pack2(w.y, w.y),
                                         pack2(w.z, w.z), pack2(w.w, w.w) };
#pragma unroll
            for (int np = 0; np < 4; np++)
#pragma unroll
                for (int jj = 0; jj < 4; jj++)
                    fma2(acc[np][jj], w2[jj], x2[np]);               // 16 fma2 / k
        }

        // ---- epilogue: unpack node pairs, add nothing (bias already in), relu, store ----
#pragma unroll
        for (int np = 0; np < 4; np++) {
            int n0 = base + wb + 2 * np;
            float4 o0, o1;
            unpack2(acc[np][0], o0.x, o1.x);
            unpack2(acc[np][1], o0.y, o1.y);
            unpack2(acc[np][2], o0.z, o1.z);
            unpack2(acc[np][3], o0.w, o1.w);
            if (RELU) {
                o0.x = fmaxf(o0.x, 0.f); o0.y = fmaxf(o0.y, 0.f);
                o0.z = fmaxf(o0.z, 0.f); o0.w = fmaxf(o0.w, 0.f);
                o1.x = fmaxf(o1.x, 0.f); o1.y = fmaxf(o1.y, 0.f);
                o1.z = fmaxf(o1.z, 0.f); o1.w = fmaxf(o1.w, 0.f);
            }
            if (n0 < NN)     *(float4*)(out + (size_t)n0 * 128 + jg) = o0;
            if (n0 + 1 < NN) *(float4*)(out + (size_t)(n0 + 1) * 128 + jg) = o1;
        }
    }
}

// ============================ launch ============================

static const int SMEM_L1 = (128 * 132 + 128 * 68) * (int)sizeof(float);   // 102400 -> 2 CTA/SM
static const int SMEM_L2 = (256 * 132 + 256 * 68) * (int)sizeof(float);   // 204800 -> 1 CTA/SM

extern "C" void kernel_launch(void* const* d_in, const int* in_sizes, int n_in,
                              void* d_out, int out_size) {
    const int*   edge = (const int*)d_in[0];
    const float* emb  = (const float*)d_in[1];
    const float* W1l  = (const float*)d_in[2];
    const float* b1l  = (const float*)d_in[3];
    const float* W1r  = (const float*)d_in[4];
    const float* W2l  = (const float*)d_in[5];
    const float* b2l  = (const float*)d_in[6];
    const float* W2r  = (const float*)d_in[7];
    float* out = (float*)d_out;

    const int* src = edge;
    const int* dst = edge + NE;

    float *agg, *deg, *h;
    cudaGetSymbolAddress((void**)&agg, g_agg);
    cudaGetSymbolAddress((void**)&deg, g_deg);
    cudaGetSymbolAddress((void**)&h,   g_h);

    cudaFuncSetAttribute(layer2x_kernel<64, true>,
                         cudaFuncAttributeMaxDynamicSharedMemorySize, SMEM_L1);
    cudaFuncSetAttribute(layer2x_kernel<128, false>,
                         cudaFuncAttributeMaxDynamicSharedMemorySize, SMEM_L2);

    // Layer 1
    zero_kernel<<<512, 256>>>((float4*)agg, NN * 64 / 4);
    zero_kernel<<<64, 256>>>((float4*)deg, NN / 4);
    scatter_kernel<64, true><<<2368, 256>>>(src, dst, emb, agg, deg);
    layer2x_kernel<64, true><<<296, 256, SMEM_L1>>>(W1l, b1l, W1r, emb, agg, deg, h);

    // Layer 2 (deg reused — graph unchanged)
    zero_kernel<<<1024, 256>>>((float4*)agg, NN * 128 / 4);
    scatter_kernel<128, false><<<2368, 256>>>(src, dst, h, agg, deg);
    layer2x_kernel<128, false><<<148, 256, SMEM_L2>>>(W2l, b2l, W2r, h, agg, deg, out);
}

// round 17
// speedup vs baseline: 1.1092x; 1.1092x over previous
#include <cuda_runtime.h>
#include <cstdint>

#define NN 50000
#define NE 640000
#define NB_SCAN 196   // ceil(NN/256)

// Scratch (allocation-free per harness rules)
__device__ float g_deg[NN];
__device__ float g_agg[NN * 128];
__device__ float g_h[NN * 128];
__device__ int   g_cnt[NN];
__device__ int   g_cur[NN];
__device__ int   g_rowptr[NN + 1];
__device__ int   g_adj[NE];
__device__ int   g_part[256];

// ============================ f32x2 helpers ============================

__device__ __forceinline__ unsigned long long pack2(float a, float b) {
    unsigned long long r;
    asm("mov.b64 %0, {%1, %2};" : "=l"(r) : "f"(a), "f"(b));
    return r;
}
__device__ __forceinline__ void unpack2(unsigned long long v, float& lo, float& hi) {
    asm("mov.b64 {%0, %1}, %2;" : "=f"(lo), "=f"(hi) : "l"(v));
}
__device__ __forceinline__ void fma2(unsigned long long& d, unsigned long long a,
                                     unsigned long long b) {
    asm("fma.rn.f32x2 %0, %1, %2, %0;" : "+l"(d) : "l"(a), "l"(b));
}

// ============================ CSR build ============================

__global__ void zero_int_kernel(int* __restrict__ p, int n) {
    int i = blockIdx.x * blockDim.x + threadIdx.x;
    if (i < n) p[i] = 0;
}

__global__ void count_kernel(const int* __restrict__ dst, int* __restrict__ cnt) {
    int i = blockIdx.x * blockDim.x + threadIdx.x;
    if (i < NE) atomicAdd(cnt + __ldg(dst + i), 1);
}

// Block-local exclusive scan; per-block totals to part[].
__global__ void scan1_kernel(const int* __restrict__ cnt, int* __restrict__ rowptr,
                             int* __restrict__ part) {
    __shared__ int s[256];
    int t = threadIdx.x;
    int i = blockIdx.x * 256 + t;
    int v = (i < NN) ? cnt[i] : 0;
    s[t] = v;
    __syncthreads();
#pragma unroll
    for (int o = 1; o < 256; o <<= 1) {
        int y = (t >= o) ? s[t - o] : 0;
        __syncthreads();
        s[t] += y;
        __syncthreads();
    }
    if (i < NN) rowptr[i] = s[t] - v;          // local exclusive
    if (t == 255) part[blockIdx.x] = s[255];   // block total
}

// Exclusive scan of the block totals (NB_SCAN <= 256), single block.
__global__ void scan2_kernel(int* __restrict__ part) {
    __shared__ int s[256];
    int t = threadIdx.x;
    int v = (t < NB_SCAN) ? part[t] : 0;
    s[t] = v;
    __syncthreads();
#pragma unroll
    for (int o = 1; o < 256; o <<= 1) {
        int y = (t >= o) ? s[t - o] : 0;
        __syncthreads();
        s[t] += y;
        __syncthreads();
    }
    if (t < NB_SCAN) part[t] = s[t] - v;       // exclusive
}

__global__ void scan3_kernel(const int* __restrict__ part, const int* __restrict__ cnt,
                             int* __restrict__ rowptr, int* __restrict__ cur,
                             float* __restrict__ deg) {
    int i = blockIdx.x * 256 + threadIdx.x;
    if (i < NN) {
        int r = rowptr[i] + part[blockIdx.x];
        rowptr[i] = r;
        cur[i] = r;
        deg[i] = (float)cnt[i];
    }
    if (i == 0) rowptr[NN] = NE;
}

__global__ void fill_kernel(const int* __restrict__ src, const int* __restrict__ dst,
                            int* __restrict__ cur, int* __restrict__ adj) {
    int i = blockIdx.x * blockDim.x + threadIdx.x;
    if (i < NE) {
        int pos = atomicAdd(cur + __ldg(dst + i), 1);
        adj[pos] = __ldg(src + i);
    }
}

// ============================ gather aggregation (no atomics) ============================

// K=64: one HALF-WARP (16 lanes) per node; 16 float4 chunks = the whole 64-float row.
// One neighbor per iteration, two 128B lines per neighbor. Writes SUM into agg.
__global__ void gather64_kernel(const int* __restrict__ rowptr, const int* __restrict__ adj,
                                const float4* __restrict__ x, float4* __restrict__ agg) {
    int hw = (blockIdx.x * blockDim.x + threadIdx.x) >> 4;   // half-warp id = node
    if (hw >= NN) return;
    int c = threadIdx.x & 15;
    int r0 = __ldg(rowptr + hw);
    int r1 = __ldg(rowptr + hw + 1);
    float4 acc = make_float4(0.f, 0.f, 0.f, 0.f);
    for (int j = r0; j < r1; j++) {
        int s = __ldg(adj + j);
        float4 v = __ldg(x + (size_t)s * 16 + c);
        acc.x += v.x; acc.y += v.y; acc.z += v.z; acc.w += v.w;
    }
    agg[(size_t)hw * 16 + c] = acc;
}

// K=128: one warp per node; 32 float4 chunks per row.
__global__ void gather128_kernel(const int* __restrict__ rowptr, const int* __restrict__ adj,
                                 const float4* __restrict__ x, float4* __restrict__ agg) {
    int warp = (blockIdx.x * blockDim.x + threadIdx.x) >> 5;
    if (warp >= NN) return;
    int c = threadIdx.x & 31;
    int r0 = __ldg(rowptr + warp);
    int r1 = __ldg(rowptr + warp + 1);
    float4 acc = make_float4(0.f, 0.f, 0.f, 0.f);
    for (int j = r0; j < r1; j++) {
        int s = __ldg(adj + j);
        float4 v = __ldg(x + (size_t)s * 32 + c);
        acc.x += v.x; acc.y += v.y; acc.z += v.z; acc.w += v.w;
    }
    agg[(size_t)warp * 32 + c] = acc;
}

// ============================ f32x2 layer kernel (smem-lean) ============================
// out[n, j] = (RELU?) b[j] + sum_k' W'[j,k']*xc[n,k'],  K' = 2*KIN (mean ‖ x),
// W' = [Wl | Wr]. K' processed in chunks of 128 k-rows (layer1: 1 chunk, layer2: 2).
// smem per chunk: Ws[128][132] transposed W-chunk, xsT[128][68] transposed x-chunk.
// Tile = 64 nodes per CTA (grid = 782, one tile each). Warp: 8 nodes (4 pairs),
// lane: 4 outputs. Per k: 2x LDS.128-broadcast (x pairs, zero movs) + 1x LDS.128 (w)
// + 4 pack movs + 16 fma2  ->  6 smem wavefronts / 16 fma2: fma-pipe bound.

template <int KIN, bool RELU>
__global__ void __launch_bounds__(256, 2)
layer3_kernel(const float* __restrict__ Wl, const float* __restrict__ bl,
              const float* __restrict__ Wr, const float* __restrict__ xin,
              const float* __restrict__ agg, const float* __restrict__ deg,
              float* __restrict__ out) {
    constexpr int K2 = 2 * KIN;
    constexpr int NCH = K2 / 128;
    constexpr int WST = 132;   // 528B rows: 16B-aligned, 2-way-max staging conflicts
    constexpr int XST = 68;    // 272B rows: 16B-aligned
    extern __shared__ float sm[];
    float* Ws  = sm;                 // 128 * 132
    float* xsT = sm + 128 * WST;     // 128 * 68

    const int tid = threadIdx.x;
    const int wid = tid >> 5;
    const int lane = tid & 31;
    const int jg = lane * 4;         // 4 consecutive outputs per lane
    const int wb = wid * 8;          // warp's 8-node base in the 64-node tile
    const int base = blockIdx.x * 64;

    unsigned long long acc[4][4];
#pragma unroll
    for (int jj = 0; jj < 4; jj++) {
        float b = __ldg(bl + jg + jj);
        unsigned long long b2 = pack2(b, b);
        acc[0][jj] = b2; acc[1][jj] = b2; acc[2][jj] = b2; acc[3][jj] = b2;
    }

    for (int ch = 0; ch < NCH; ch++) {
        if (ch) __syncthreads();     // previous chunk's readers done before overwrite
        const int kb = ch * 128;

        // ---- stage W chunk transposed: thread -> (j, k-quad) ----
        for (int i = tid; i < 128 * 32; i += 256) {
            int j = i >> 5;
            int kc = (i & 31) << 2;
            int gk = kb + kc;
            float4 v = (gk < KIN) ? __ldg((const float4*)(Wl + j * KIN + gk))
                                  : __ldg((const float4*)(Wr + j * KIN + (gk - KIN)));
            Ws[(kc + 0) * WST + j] = v.x;
            Ws[(kc + 1) * WST + j] = v.y;
            Ws[(kc + 2) * WST + j] = v.z;
            Ws[(kc + 3) * WST + j] = v.w;
        }
        // ---- stage x chunk transposed: thread -> (node, k-quad) ----
        for (int i = tid; i < 64 * 32; i += 256) {
            int nl = i >> 5;
            int kc = (i & 31) << 2;
            int gk = kb + kc;
            int node = base + nl;
            float4 v = make_float4(0.f, 0.f, 0.f, 0.f);
            if (node < NN) {
                if (gk < KIN) {
                    v = __ldg((const float4*)agg + (size_t)node * (KIN / 4) + (gk >> 2));
                    float inv = 1.0f / fmaxf(__ldg(deg + node), 1.0f);
                    v.x *= inv; v.y *= inv; v.z *= inv; v.w *= inv;
                } else {
                    v = __ldg((const float4*)xin + (size_t)node * (KIN / 4) + ((gk - KIN) >> 2));
                }
            }
            xsT[(kc + 0) * XST + nl] = v.x;
            xsT[(kc + 1) * XST + nl] = v.y;
            xsT[(kc + 2) * XST + nl] = v.z;
            xsT[(kc + 3) * XST + nl] = v.w;
        }
        __syncthreads();

#pragma unroll 4
        for (int kc = 0; kc < 128; kc++) {
            // x: 4 node-pairs = 32B, two LDS.128 broadcasts, pre-packed pairs
            const ulonglong2* xp = (const ulonglong2*)(xsT + kc * XST + wb);
            ulonglong2 xa = xp[0];
            ulonglong2 xb = xp[1];
            float4 w = *(const float4*)(Ws + kc * WST + jg);
            unsigned long long w0 = pack2(w.x, w.x);
            unsigned long long w1 = pack2(w.y, w.y);
            unsigned long long w2 = pack2(w.z, w.z);
            unsigned long long w3 = pack2(w.w, w.w);
            fma2(acc[0][0], w0, xa.x); fma2(acc[0][1], w1, xa.x);
            fma2(acc[0][2], w2, xa.x); fma2(acc[0][3], w3, xa.x);
            fma2(acc[1][0], w0, xa.y); fma2(acc[1][1], w1, xa.y);
            fma2(acc[1][2], w2, xa.y); fma2(acc[1][3], w3, xa.y);
            fma2(acc[2][0], w0, xb.x); fma2(acc[2][1], w1, xb.x);
            fma2(acc[2][2], w2, xb.x); fma2(acc[2][3], w3, xb.x);
            fma2(acc[3][0], w0, xb.y); fma2(acc[3][1], w1, xb.y);
            fma2(acc[3][2], w2, xb.y); fma2(acc[3][3], w3, xb.y);
        }
    }

    // ---- epilogue ----
#pragma unroll
    for (int np = 0; np < 4; np++) {
        int n0 = base + wb + 2 * np;
        float4 o0, o1;
        unpack2(acc[np][0], o0.x, o1.x);
        unpack2(acc[np][1], o0.y, o1.y);
        unpack2(acc[np][2], o0.z, o1.z);
        unpack2(acc[np][3], o0.w, o1.w);
        if (RELU) {
            o0.x = fmaxf(o0.x, 0.f); o0.y = fmaxf(o0.y, 0.f);
            o0.z = fmaxf(o0.z, 0.f); o0.w = fmaxf(o0.w, 0.f);
            o1.x = fmaxf(o1.x, 0.f); o1.y = fmaxf(o1.y, 0.f);
            o1.z = fmaxf(o1.z, 0.f); o1.w = fmaxf(o1.w, 0.f);
        }
        if (n0 < NN)     *(float4*)(out + (size_t)n0 * 128 + jg) = o0;
        if (n0 + 1 < NN) *(float4*)(out + (size_t)(n0 + 1) * 128 + jg) = o1;
    }
}

// ============================ launch ============================

static const int SMEM_L = (128 * 132 + 128 * 68) * (int)sizeof(float);  // 102400
static const int NTILES = (NN + 63) / 64;                               // 782

extern "C" void kernel_launch(void* const* d_in, const int* in_sizes, int n_in,
                              void* d_out, int out_size) {
    const int*   edge = (const int*)d_in[0];
    const float* emb  = (const float*)d_in[1];
    const float* W1l  = (const float*)d_in[2];
    const float* b1l  = (const float*)d_in[3];
    const float* W1r  = (const float*)d_in[4];
    const float* W2l  = (const float*)d_in[5];
    const float* b2l  = (const float*)d_in[6];
    const float* W2r  = (const float*)d_in[7];
    float* out = (float*)d_out;

    const int* src = edge;
    const int* dst = edge + NE;

    float *agg, *deg, *h;
    int *cnt, *cur, *rowptr, *adj, *part;
    cudaGetSymbolAddress((void**)&agg, g_agg);
    cudaGetSymbolAddress((void**)&deg, g_deg);
    cudaGetSymbolAddress((void**)&h,   g_h);
    cudaGetSymbolAddress((void**)&cnt, g_cnt);
    cudaGetSymbolAddress((void**)&cur, g_cur);
    cudaGetSymbolAddress((void**)&rowptr, g_rowptr);
    cudaGetSymbolAddress((void**)&adj, g_adj);
    cudaGetSymbolAddress((void**)&part, g_part);

    cudaFuncSetAttribute(layer3_kernel<64, true>,
                         cudaFuncAttributeMaxDynamicSharedMemorySize, SMEM_L);
    cudaFuncSetAttribute(layer3_kernel<128, false>,
                         cudaFuncAttributeMaxDynamicSharedMemorySize, SMEM_L);

    // ---- CSR build (once, reused by both layers) ----
    zero_int_kernel<<<NB_SCAN, 256>>>(cnt, NN);
    count_kernel<<<(NE + 255) / 256, 256>>>(dst, cnt);
    scan1_kernel<<<NB_SCAN, 256>>>(cnt, rowptr, part);
    scan2_kernel<<<1, 256>>>(part);
    scan3_kernel<<<NB_SCAN, 256>>>(part, cnt, rowptr, cur, deg);
    fill_kernel<<<(NE + 255) / 256, 256>>>(src, dst, cur, adj);

    // ---- Layer 1 ----  (half-warp per node: NN*16 threads)
    gather64_kernel<<<(NN * 16 + 255) / 256, 256>>>(rowptr, adj, (const float4*)emb,
                                                    (float4*)agg);
    layer3_kernel<64, true><<<NTILES, 256, SMEM_L>>>(W1l, b1l, W1r, emb, agg, deg, h);

    // ---- Layer 2 ----  (warp per node: NN*32 threads)
    gather128_kernel<<<(NN * 32 + 255) / 256, 256>>>(rowptr, adj, (const float4*)h,
                                                     (float4*)agg);
    layer3_kernel<128, false><<<NTILES, 256, SMEM_L>>>(W2l, b2l, W2r, h, agg, deg, out);
}